// round 3
// baseline (speedup 1.0000x reference)
#include <cuda_runtime.h>
#include <cuda_bf16.h>
#include <cstdint>

// ---------------------------------------------------------------------------
// GraphSAGE 2-layer backbone.
//   deg[dst] += 1 per edge ; deg_inv = 1/max(deg,1)
//   agg1 = scatter_add(x[src] -> dst) * deg_inv
//   h    = relu(agg1 @ W1_l^T + b1 + x @ W1_r^T)
//   agg2 = scatter_add(h[src] -> dst) * deg_inv
//   out  = agg2 @ W2_l^T + b2 + h @ W2_r^T
// Inputs: x[N,64] f32, edge_index[2,E] int32 (JAX x64 disabled!), W1_l[128,64],
//         b1[128], W1_r[128,64], W2_l[128,128], b2[128], W2_r[128,128]
// Output: [N,128] f32
// ---------------------------------------------------------------------------

static constexpr int NN   = 100000;
static constexpr int F_IN = 64;
static constexpr int F_H  = 128;

// scratch (static __device__ — no allocations allowed)
__device__ __align__(16) float g_agg1[(size_t)NN * F_IN];
__device__ __align__(16) float g_h   [(size_t)NN * F_H];
__device__ __align__(16) float g_agg2[(size_t)NN * F_H];
__device__ __align__(16) float g_deg [NN];
__device__ __align__(16) float g_w1t [2 * F_IN * 128];   // [2K][128], K=64
__device__ __align__(16) float g_w2t [2 * F_H  * 128];   // [2K][128], K=128

// ---------------------------------------------------------------------------
__global__ void zero4_kernel(float4* p, int n4) {
    int i = blockIdx.x * blockDim.x + threadIdx.x;
    int stride = gridDim.x * blockDim.x;
    float4 z = make_float4(0.f, 0.f, 0.f, 0.f);
    for (; i < n4; i += stride) p[i] = z;
}

// Pack W_l,W_r (each [128,K] row-major) into WcT[k][j]:
//   WcT[k*128+j] = (k<K) ? W_l[j*K+k] : W_r[j*K+(k-K)]
template <int K>
__global__ void pack_kernel(const float* __restrict__ Wl,
                            const float* __restrict__ Wr,
                            float* __restrict__ WcT) {
    int i = blockIdx.x * blockDim.x + threadIdx.x;
    if (i >= 2 * K * 128) return;
    int k = i >> 7;
    int j = i & 127;
    WcT[i] = (k < K) ? Wl[j * K + k] : Wr[j * K + (k - K)];
}

// Edge scatter: one thread = (edge, float4-chunk). F4 = F/4 (16 or 32).
// Gathers in[src] as float4 (coalesced within warp), 4 scalar REDs into agg[dst].
template <int F4, bool COUNT_DEG>
__global__ void agg_kernel(const float4* __restrict__ in4,
                           const int* __restrict__ ei,
                           int E, int nnodes,
                           float* __restrict__ agg,
                           float* __restrict__ deg) {
    int idx = blockIdx.x * blockDim.x + threadIdx.x;
    if (idx >= E * F4) return;
    int e = idx / F4;
    int q = idx - e * F4;
    int src = __ldg(&ei[e]);
    int dst = __ldg(&ei[E + e]);
    // guard: never emit a wild atomic address even if dtype assumptions are off
    if ((unsigned)src >= (unsigned)nnodes || (unsigned)dst >= (unsigned)nnodes) return;
    float4 v = __ldg(&in4[(size_t)src * F4 + q]);
    float* p = agg + ((size_t)dst * F4 + q) * 4;
    atomicAdd(p + 0, v.x);
    atomicAdd(p + 1, v.y);
    atomicAdd(p + 2, v.z);
    atomicAdd(p + 3, v.w);
    if (COUNT_DEG && q == 0) atomicAdd(deg + dst, 1.0f);
}

// Fused dense layer: out[n][j] = act( sum_k cat(agg*di, x)[n][k] * WcT[k][j] + b[j] )
// blockDim=256 (8 warps). Tile = 64 nodes. Each warp: 8 nodes, each lane: 4 j's.
template <int K, bool RELU>
__global__ void dense_kernel(const float* __restrict__ xin,
                             const float* __restrict__ agg,
                             const float* __restrict__ deg,
                             const float* __restrict__ WcT,
                             const float* __restrict__ bias,
                             float* __restrict__ out,
                             int nnodes) {
    constexpr int K2 = 2 * K;
    extern __shared__ float sm[];
    float* sW = sm;                 // K2*128 floats, layout [k][j]
    float* sC = sm + K2 * 128;      // 64 nodes * K2, layout [n][k]
    __shared__ float sB[128];
    __shared__ float sDi[64];

    const int tid  = threadIdx.x;
    const int base = blockIdx.x * 64;

    // stage deg_inv
    if (tid < 64) {
        int node = base + tid;
        float d = (node < nnodes) ? deg[node] : 1.0f;
        sDi[tid] = 1.0f / fmaxf(d, 1.0f);
    }
    if (tid < 128) sB[tid] = bias[tid];
    // stage weights (coalesced, conflict-free writes)
    for (int i = tid; i < K2 * 128; i += 256) sW[i] = WcT[i];
    __syncthreads();

    // stage concat input tile [n][0..K-1]=agg*di, [n][K..2K-1]=x
    for (int i = tid; i < 64 * K; i += 256) {
        int n = i / K;
        int k = i - n * K;
        int node = base + n;
        float xv = 0.f, av = 0.f;
        if (node < nnodes) {
            size_t off = (size_t)node * K + k;
            xv = xin[off];
            av = agg[off] * sDi[n];
        }
        sC[n * K2 + k]     = av;
        sC[n * K2 + K + k] = xv;
    }
    __syncthreads();

    const int w = tid >> 5;          // warp id: nodes w*8 .. w*8+7
    const int l = tid & 31;          // lane: output features 4l..4l+3

    float acc[8][4];
#pragma unroll
    for (int m = 0; m < 8; m++) {
        acc[m][0] = sB[4 * l];
        acc[m][1] = sB[4 * l + 1];
        acc[m][2] = sB[4 * l + 2];
        acc[m][3] = sB[4 * l + 3];
    }

    const float4* sW4 = reinterpret_cast<const float4*>(sW);
    const float*  sCw = sC + (w * 8) * K2;

#pragma unroll 4
    for (int k = 0; k < K2; k++) {
        float4 wv = sW4[k * 32 + l];      // conflict-free LDS.128
#pragma unroll
        for (int m = 0; m < 8; m++) {
            float c = sCw[m * K2 + k];    // broadcast LDS
            acc[m][0] += c * wv.x;
            acc[m][1] += c * wv.y;
            acc[m][2] += c * wv.z;
            acc[m][3] += c * wv.w;
        }
    }

#pragma unroll
    for (int m = 0; m < 8; m++) {
        int node = base + w * 8 + m;
        if (node >= nnodes) continue;
        float4 o;
        o.x = acc[m][0]; o.y = acc[m][1]; o.z = acc[m][2]; o.w = acc[m][3];
        if (RELU) {
            o.x = fmaxf(o.x, 0.f); o.y = fmaxf(o.y, 0.f);
            o.z = fmaxf(o.z, 0.f); o.w = fmaxf(o.w, 0.f);
        }
        reinterpret_cast<float4*>(out)[(size_t)node * 32 + l] = o;
    }
}

// ---------------------------------------------------------------------------
extern "C" void kernel_launch(void* const* d_in, const int* in_sizes, int n_in,
                              void* d_out, int out_size) {
    const float* x    = (const float*)d_in[0];
    const int*   ei   = (const int*)d_in[1];      // int32! (JAX x64 disabled)
    const float* W1_l = (const float*)d_in[2];
    const float* b1   = (const float*)d_in[3];
    const float* W1_r = (const float*)d_in[4];
    const float* W2_l = (const float*)d_in[5];
    const float* b2   = (const float*)d_in[6];
    const float* W2_r = (const float*)d_in[7];
    float*       out  = (float*)d_out;

    const int n = in_sizes[0] / F_IN;   // 100000
    const int E = in_sizes[1] / 2;      // 1600000

    // scratch pointers (static __device__ globals)
    void *p_agg1, *p_h, *p_agg2, *p_deg, *p_w1t, *p_w2t;
    cudaGetSymbolAddress(&p_agg1, g_agg1);
    cudaGetSymbolAddress(&p_h,    g_h);
    cudaGetSymbolAddress(&p_agg2, g_agg2);
    cudaGetSymbolAddress(&p_deg,  g_deg);
    cudaGetSymbolAddress(&p_w1t,  g_w1t);
    cudaGetSymbolAddress(&p_w2t,  g_w2t);
    float* agg1 = (float*)p_agg1;
    float* h    = (float*)p_h;
    float* agg2 = (float*)p_agg2;
    float* deg  = (float*)p_deg;
    float* w1t  = (float*)p_w1t;
    float* w2t  = (float*)p_w2t;

    const int smem1 = (2 * F_IN * 128 + 64 * 2 * F_IN) * (int)sizeof(float); //  96KB
    const int smem2 = (2 * F_H  * 128 + 64 * 2 * F_H ) * (int)sizeof(float); // 192KB
    cudaFuncSetAttribute(dense_kernel<F_IN, true>,
                         cudaFuncAttributeMaxDynamicSharedMemorySize, smem1);
    cudaFuncSetAttribute(dense_kernel<F_H, false>,
                         cudaFuncAttributeMaxDynamicSharedMemorySize, smem2);

    // 1) pack weights transposed: WcT[k][j]
    pack_kernel<F_IN><<<(2 * F_IN * 128 + 255) / 256, 256>>>(W1_l, W1_r, w1t);
    pack_kernel<F_H ><<<(2 * F_H  * 128 + 255) / 256, 256>>>(W2_l, W2_r, w2t);

    // 2) zero scratch accumulators
    zero4_kernel<<<2048, 256>>>((float4*)agg1, n * (F_IN / 4));
    zero4_kernel<<<2048, 256>>>((float4*)agg2, n * (F_H / 4));
    zero4_kernel<<<256,  256>>>((float4*)deg,  n / 4);

    // 3) layer-1 aggregation (+ degree count)
    {
        int items = E * (F_IN / 4);
        agg_kernel<F_IN / 4, true><<<(items + 255) / 256, 256>>>(
            (const float4*)x, ei, E, n, agg1, deg);
    }

    // 4) layer-1 dense + relu -> h
    dense_kernel<F_IN, true><<<(n + 63) / 64, 256, smem1>>>(
        x, agg1, deg, w1t, b1, h, n);

    // 5) layer-2 aggregation
    {
        int items = E * (F_H / 4);
        agg_kernel<F_H / 4, false><<<(items + 255) / 256, 256>>>(
            (const float4*)h, ei, E, n, agg2, nullptr);
    }

    // 6) layer-2 dense -> out
    dense_kernel<F_H, false><<<(n + 63) / 64, 256, smem2>>>(
        h, agg2, deg, w2t, b2, out, n);
}

// round 4
// speedup vs baseline: 1.4318x; 1.4318x over previous
#include <cuda_runtime.h>
#include <cuda_bf16.h>
#include <cstdint>

// ---------------------------------------------------------------------------
// GraphSAGE 2-layer backbone, CSR gather-reduce formulation (no float atomics).
//   deg = histogram(dst); row_ptr = exscan(deg); csr_src = counting-sort(src by dst)
//   agg1[n] = (1/max(deg,1)) * sum_{j in row n} x[csr_src[j]]
//   h    = relu([agg1, x] @ [W1_l;W1_r]^T + b1)
//   agg2[n] = (1/max(deg,1)) * sum_{j in row n} h[csr_src[j]]
//   out  = [agg2, h] @ [W2_l;W2_r]^T + b2
// Inputs: x[N,64] f32, edge_index[2,E] int32, W1_l[128,64], b1[128],
//         W1_r[128,64], W2_l[128,128], b2[128], W2_r[128,128]
// Output: [N,128] f32
// ---------------------------------------------------------------------------

static constexpr int NN   = 100000;
static constexpr int EE   = 1600000;
static constexpr int F_IN = 64;
static constexpr int F_H  = 128;

// scratch (static __device__ — no allocations allowed)
__device__ __align__(16) float g_agg1 [(size_t)NN * F_IN];
__device__ __align__(16) float g_h    [(size_t)NN * F_H];
__device__ __align__(16) float g_agg2 [(size_t)NN * F_H];
__device__ __align__(16) float g_dinv [NN];
__device__ __align__(16) int   g_degi [NN];
__device__ __align__(16) int   g_rowp [NN + 1];
__device__ __align__(16) int   g_curs [NN];
__device__ __align__(16) int   g_csr  [EE];
__device__ __align__(16) float g_w1t  [2 * F_IN * 128];   // [2K][128], K=64
__device__ __align__(16) float g_w2t  [2 * F_H  * 128];   // [2K][128], K=128

// ---------------------------------------------------------------------------
__global__ void zero_int_kernel(int* p, int n) {
    int i = blockIdx.x * blockDim.x + threadIdx.x;
    if (i < n) p[i] = 0;
}

// Pack W_l,W_r (each [128,K] row-major) into WcT[k][j]
template <int K>
__global__ void pack_kernel(const float* __restrict__ Wl,
                            const float* __restrict__ Wr,
                            float* __restrict__ WcT) {
    int i = blockIdx.x * blockDim.x + threadIdx.x;
    if (i >= 2 * K * 128) return;
    int k = i >> 7;
    int j = i & 127;
    WcT[i] = (k < K) ? Wl[j * K + k] : Wr[j * K + (k - K)];
}

// Histogram of dst
__global__ void hist_kernel(const int* __restrict__ ei, int E, int nnodes,
                            int* __restrict__ degi) {
    int e = blockIdx.x * blockDim.x + threadIdx.x;
    if (e >= E) return;
    int dst = __ldg(&ei[E + e]);
    if ((unsigned)dst < (unsigned)nnodes) atomicAdd(&degi[dst], 1);
}

// Single-block exclusive scan over deg (98 items/thread + Hillis-Steele),
// producing row_ptr, cursor copy and deg_inv.
__global__ void scan_kernel(const int* __restrict__ degi,
                            int* __restrict__ rowp,
                            int* __restrict__ curs,
                            float* __restrict__ dinv,
                            int n, int E) {
    __shared__ int ssum[1024];
    const int t = threadIdx.x;
    const int ITEMS = (n + 1023) / 1024;
    const int beg = t * ITEMS;
    const int end = min(beg + ITEMS, n);

    int s = 0;
    for (int i = beg; i < end; i++) s += degi[i];
    ssum[t] = s;
    __syncthreads();
    for (int off = 1; off < 1024; off <<= 1) {
        int v = (t >= off) ? ssum[t - off] : 0;
        __syncthreads();
        ssum[t] += v;
        __syncthreads();
    }
    int run = (t == 0) ? 0 : ssum[t - 1];
    for (int i = beg; i < end; i++) {
        int d = degi[i];
        rowp[i] = run;
        curs[i] = run;
        dinv[i] = 1.0f / fmaxf((float)d, 1.0f);
        run += d;
    }
    if (t == 1023) rowp[n] = ssum[1023];
}

// Counting-sort scatter: csr[pos] = src, pos = cursor[dst]++
__global__ void scatter_kernel(const int* __restrict__ ei, int E, int nnodes,
                               int* __restrict__ curs,
                               int* __restrict__ csr) {
    int e = blockIdx.x * blockDim.x + threadIdx.x;
    if (e >= E) return;
    int src = __ldg(&ei[e]);
    int dst = __ldg(&ei[E + e]);
    if ((unsigned)src >= (unsigned)nnodes || (unsigned)dst >= (unsigned)nnodes) return;
    int pos = atomicAdd(&curs[dst], 1);
    csr[pos] = src;
}

// Gather-reduce mean aggregation. One group of F4 lanes per node;
// each lane owns one float4 column chunk. 2-way unroll for MLP.
template <int F4>
__global__ void gather_agg_kernel(const float4* __restrict__ in4,
                                  const int* __restrict__ rowp,
                                  const int* __restrict__ csr,
                                  const float* __restrict__ dinv,
                                  float4* __restrict__ aggout,
                                  int n) {
    constexpr int GPB = 256 / F4;
    const int node = blockIdx.x * GPB + (threadIdx.x / F4);
    const int lane = threadIdx.x & (F4 - 1);
    if (node >= n) return;

    const int beg = __ldg(&rowp[node]);
    const int end = __ldg(&rowp[node + 1]);

    float4 a0 = make_float4(0.f, 0.f, 0.f, 0.f);
    float4 a1 = make_float4(0.f, 0.f, 0.f, 0.f);

    int j = beg;
    for (; j + 2 <= end; j += 2) {
        int s0 = __ldg(&csr[j]);
        int s1 = __ldg(&csr[j + 1]);
        float4 v0 = __ldg(&in4[(size_t)s0 * F4 + lane]);
        float4 v1 = __ldg(&in4[(size_t)s1 * F4 + lane]);
        a0.x += v0.x; a0.y += v0.y; a0.z += v0.z; a0.w += v0.w;
        a1.x += v1.x; a1.y += v1.y; a1.z += v1.z; a1.w += v1.w;
    }
    if (j < end) {
        int s0 = __ldg(&csr[j]);
        float4 v0 = __ldg(&in4[(size_t)s0 * F4 + lane]);
        a0.x += v0.x; a0.y += v0.y; a0.z += v0.z; a0.w += v0.w;
    }

    const float di = __ldg(&dinv[node]);
    float4 r;
    r.x = (a0.x + a1.x) * di;
    r.y = (a0.y + a1.y) * di;
    r.z = (a0.z + a1.z) * di;
    r.w = (a0.w + a1.w) * di;
    aggout[(size_t)node * F4 + lane] = r;
}

// Fused dense layer: out[n][j] = act( sum_k cat(agg, x)[n][k] * WcT[k][j] + b[j] )
// (agg already mean-scaled). blockDim=256. Tile = 64 nodes.
template <int K, bool RELU>
__global__ void dense_kernel(const float* __restrict__ xin,
                             const float* __restrict__ agg,
                             const float* __restrict__ WcT,
                             const float* __restrict__ bias,
                             float* __restrict__ out,
                             int nnodes) {
    constexpr int K2 = 2 * K;
    extern __shared__ float sm[];
    float* sW = sm;                 // K2*128 floats, layout [k][j]
    float* sC = sm + K2 * 128;      // 64 nodes * K2, layout [n][k]
    __shared__ float sB[128];

    const int tid  = threadIdx.x;
    const int base = blockIdx.x * 64;

    if (tid < 128) sB[tid] = bias[tid];
    for (int i = tid; i < K2 * 128; i += 256) sW[i] = WcT[i];

    for (int i = tid; i < 64 * K; i += 256) {
        int n = i / K;
        int k = i - n * K;
        int node = base + n;
        float xv = 0.f, av = 0.f;
        if (node < nnodes) {
            size_t off = (size_t)node * K + k;
            xv = xin[off];
            av = agg[off];
        }
        sC[n * K2 + k]     = av;
        sC[n * K2 + K + k] = xv;
    }
    __syncthreads();

    const int w = tid >> 5;          // warp: nodes w*8 .. w*8+7
    const int l = tid & 31;          // lane: output features 4l..4l+3

    float acc[8][4];
#pragma unroll
    for (int m = 0; m < 8; m++) {
        acc[m][0] = sB[4 * l];
        acc[m][1] = sB[4 * l + 1];
        acc[m][2] = sB[4 * l + 2];
        acc[m][3] = sB[4 * l + 3];
    }

    const float4* sW4 = reinterpret_cast<const float4*>(sW);
    const float*  sCw = sC + (w * 8) * K2;

#pragma unroll 4
    for (int k = 0; k < K2; k++) {
        float4 wv = sW4[k * 32 + l];      // conflict-free LDS.128
#pragma unroll
        for (int m = 0; m < 8; m++) {
            float c = sCw[m * K2 + k];    // broadcast LDS
            acc[m][0] += c * wv.x;
            acc[m][1] += c * wv.y;
            acc[m][2] += c * wv.z;
            acc[m][3] += c * wv.w;
        }
    }

#pragma unroll
    for (int m = 0; m < 8; m++) {
        int node = base + w * 8 + m;
        if (node >= nnodes) continue;
        float4 o;
        o.x = acc[m][0]; o.y = acc[m][1]; o.z = acc[m][2]; o.w = acc[m][3];
        if (RELU) {
            o.x = fmaxf(o.x, 0.f); o.y = fmaxf(o.y, 0.f);
            o.z = fmaxf(o.z, 0.f); o.w = fmaxf(o.w, 0.f);
        }
        reinterpret_cast<float4*>(out)[(size_t)node * 32 + l] = o;
    }
}

// ---------------------------------------------------------------------------
extern "C" void kernel_launch(void* const* d_in, const int* in_sizes, int n_in,
                              void* d_out, int out_size) {
    const float* x    = (const float*)d_in[0];
    const int*   ei   = (const int*)d_in[1];      // int32 (JAX x64 disabled)
    const float* W1_l = (const float*)d_in[2];
    const float* b1   = (const float*)d_in[3];
    const float* W1_r = (const float*)d_in[4];
    const float* W2_l = (const float*)d_in[5];
    const float* b2   = (const float*)d_in[6];
    const float* W2_r = (const float*)d_in[7];
    float*       out  = (float*)d_out;

    const int n = in_sizes[0] / F_IN;   // 100000
    const int E = in_sizes[1] / 2;      // 1600000

    void *p_agg1, *p_h, *p_agg2, *p_dinv, *p_degi, *p_rowp, *p_curs, *p_csr,
         *p_w1t, *p_w2t;
    cudaGetSymbolAddress(&p_agg1, g_agg1);
    cudaGetSymbolAddress(&p_h,    g_h);
    cudaGetSymbolAddress(&p_agg2, g_agg2);
    cudaGetSymbolAddress(&p_dinv, g_dinv);
    cudaGetSymbolAddress(&p_degi, g_degi);
    cudaGetSymbolAddress(&p_rowp, g_rowp);
    cudaGetSymbolAddress(&p_curs, g_curs);
    cudaGetSymbolAddress(&p_csr,  g_csr);
    cudaGetSymbolAddress(&p_w1t,  g_w1t);
    cudaGetSymbolAddress(&p_w2t,  g_w2t);
    float* agg1 = (float*)p_agg1;
    float* h    = (float*)p_h;
    float* agg2 = (float*)p_agg2;
    float* dinv = (float*)p_dinv;
    int*   degi = (int*)p_degi;
    int*   rowp = (int*)p_rowp;
    int*   curs = (int*)p_curs;
    int*   csr  = (int*)p_csr;
    float* w1t  = (float*)p_w1t;
    float* w2t  = (float*)p_w2t;

    const int smem1 = (2 * F_IN * 128 + 64 * 2 * F_IN) * (int)sizeof(float); //  96KB
    const int smem2 = (2 * F_H  * 128 + 64 * 2 * F_H ) * (int)sizeof(float); // 192KB
    cudaFuncSetAttribute(dense_kernel<F_IN, true>,
                         cudaFuncAttributeMaxDynamicSharedMemorySize, smem1);
    cudaFuncSetAttribute(dense_kernel<F_H, false>,
                         cudaFuncAttributeMaxDynamicSharedMemorySize, smem2);

    // 1) weight packing (independent of graph work)
    pack_kernel<F_IN><<<(2 * F_IN * 128 + 255) / 256, 256>>>(W1_l, W1_r, w1t);
    pack_kernel<F_H ><<<(2 * F_H  * 128 + 255) / 256, 256>>>(W2_l, W2_r, w2t);

    // 2) CSR build: histogram -> scan -> counting-sort scatter
    zero_int_kernel<<<(n + 255) / 256, 256>>>(degi, n);
    hist_kernel<<<(E + 255) / 256, 256>>>(ei, E, n, degi);
    scan_kernel<<<1, 1024>>>(degi, rowp, curs, dinv, n, E);
    scatter_kernel<<<(E + 255) / 256, 256>>>(ei, E, n, curs, csr);

    // 3) layer-1 aggregation (gather-reduce, mean folded in)
    gather_agg_kernel<F_IN / 4><<<(n * (F_IN / 4) + 255) / 256, 256>>>(
        (const float4*)x, rowp, csr, dinv, (float4*)agg1, n);

    // 4) layer-1 dense + relu -> h
    dense_kernel<F_IN, true><<<(n + 63) / 64, 256, smem1>>>(
        x, agg1, w1t, b1, h, n);

    // 5) layer-2 aggregation
    gather_agg_kernel<F_H / 4><<<(n * (F_H / 4) + 255) / 256, 256>>>(
        (const float4*)h, rowp, csr, dinv, (float4*)agg2, n);

    // 6) layer-2 dense -> out
    dense_kernel<F_H, false><<<(n + 63) / 64, 256, smem2>>>(
        h, agg2, w2t, b2, out, n);
}